// round 16
// baseline (speedup 1.0000x reference)
#include <cuda_runtime.h>
#include <math.h>
#include <stdint.h>

// ---------------------------------------------------------------------------
// Problem constants (fixed shapes from the reference)
// ---------------------------------------------------------------------------
#define D_MODEL 1024
#define NHEADS  16
#define HDIM    64
#define NKER    21
#define B_      4
#define L_      1024
#define BL      (B_ * L_)          // 4096 rows
#define BIAS_W  (2 * L_ - 1)       // 2047

// ---------------------------------------------------------------------------
// Scratch (device globals -- no allocation allowed)
// ---------------------------------------------------------------------------
__device__ float g_q   [(size_t)B_ * NHEADS * L_ * HDIM];   // [b][h][l][d]
__device__ float g_k   [(size_t)B_ * NHEADS * L_ * HDIM];
__device__ float g_v   [(size_t)B_ * NHEADS * L_ * HDIM];
__device__ float g_attn[(size_t)BL * D_MODEL];              // [b*l][h*64+d]
__device__ float g_gate[(size_t)BL * 2 * D_MODEL];          // [b*l][2048]
__device__ float g_biastab[NHEADS * BIAS_W];                // [h][rel]

// ---------------------------------------------------------------------------
// TISA bias table: bias[h][r] = sum_j amp*exp(-|sharp|*(d-off)^2), d = r-(L-1)
// ---------------------------------------------------------------------------
__global__ void tisa_bias_kernel(const float* __restrict__ amp,
                                 const float* __restrict__ off,
                                 const float* __restrict__ sharp)
{
    int r = blockIdx.x * blockDim.x + threadIdx.x;
    int h = blockIdx.y;
    if (r >= BIAS_W) return;
    float d = (float)(r - (L_ - 1));
    float s = 0.0f;
#pragma unroll
    for (int j = 0; j < NKER; j++) {
        float a  = amp  [h * NKER + j];
        float o  = off  [h * NKER + j];
        float sh = fabsf(sharp[h * NKER + j]);
        float dd = d - o;
        s += a * expf(-sh * dd * dd);
    }
    g_biastab[h * BIAS_W + r] = s;
}

// ---------------------------------------------------------------------------
// SGEMM: C = A(MxK) * B(KxN) [+bias], 128x128 tile, BK=16, 256 threads,
// 8x8 per-thread microtile, float4 shared paths.
// MODE 0: epilogue scatters into g_q  (head-major [b][h][l][d])
// MODE 1: epilogue scatters into g_k / g_v (cols <1024 -> K, >=1024 -> V)
// MODE 2: A is taken from g_attn, adds bg, writes g_gate row-major
// ---------------------------------------------------------------------------
template <int MODE>
__global__ __launch_bounds__(256)
void sgemm_kernel(const float* __restrict__ Aext,
                  const float* __restrict__ Bmat,
                  const float* __restrict__ bias,
                  int M, int N, int K)
{
    const float* __restrict__ A = (MODE == 2) ? (const float*)g_attn : Aext;

    __shared__ float As[16][128];   // A tile, transposed: As[k][m]
    __shared__ float Bs[16][128];   // B tile: Bs[k][n]

    const int tid  = threadIdx.x;
    const int bm   = blockIdx.y * 128;
    const int bn   = blockIdx.x * 128;
    const int tx   = tid & 15;
    const int ty   = tid >> 4;
    const int row0 = ty * 8;
    const int col0 = tx * 8;

    const int a_row = tid >> 2;          // 0..63
    const int a_col = (tid & 3) << 2;    // 0,4,8,12
    const int b_row = tid >> 5;          // 0..7
    const int b_col = (tid & 31) << 2;   // 0..124

    float acc[8][8];
#pragma unroll
    for (int i = 0; i < 8; i++)
#pragma unroll
        for (int j = 0; j < 8; j++) acc[i][j] = 0.0f;

    for (int k0 = 0; k0 < K; k0 += 16) {
        // load A tile (transpose into shared)
#pragma unroll
        for (int r = 0; r < 2; r++) {
            int row = a_row + r * 64;
            float4 v = *(const float4*)(A + (size_t)(bm + row) * K + (k0 + a_col));
            As[a_col + 0][row] = v.x;
            As[a_col + 1][row] = v.y;
            As[a_col + 2][row] = v.z;
            As[a_col + 3][row] = v.w;
        }
        // load B tile
#pragma unroll
        for (int r = 0; r < 2; r++) {
            int row = b_row + r * 8;
            *(float4*)(&Bs[row][b_col]) =
                *(const float4*)(Bmat + (size_t)(k0 + row) * N + (bn + b_col));
        }
        __syncthreads();

#pragma unroll
        for (int kk = 0; kk < 16; kk++) {
            float4 a0 = *(const float4*)(&As[kk][row0]);
            float4 a1 = *(const float4*)(&As[kk][row0 + 4]);
            float4 b0 = *(const float4*)(&Bs[kk][col0]);
            float4 b1 = *(const float4*)(&Bs[kk][col0 + 4]);
            float a[8] = {a0.x, a0.y, a0.z, a0.w, a1.x, a1.y, a1.z, a1.w};
            float b[8] = {b0.x, b0.y, b0.z, b0.w, b1.x, b1.y, b1.z, b1.w};
#pragma unroll
            for (int i = 0; i < 8; i++)
#pragma unroll
                for (int j = 0; j < 8; j++)
                    acc[i][j] = fmaf(a[i], b[j], acc[i][j]);
        }
        __syncthreads();
    }

    // epilogue: float4 stores; each 4-col group stays inside one head (64-aligned)
#pragma unroll
    for (int i = 0; i < 8; i++) {
        int m = bm + row0 + i;
#pragma unroll
        for (int jh = 0; jh < 2; jh++) {
            int n = bn + col0 + jh * 4;
            float4 c = make_float4(acc[i][jh * 4 + 0], acc[i][jh * 4 + 1],
                                   acc[i][jh * 4 + 2], acc[i][jh * 4 + 3]);
            if (MODE == 0) {
                int b = m >> 10, l = m & 1023;
                int h = n >> 6,  d = n & 63;
                *(float4*)(g_q + ((((size_t)b * NHEADS + h) * L_ + l) * HDIM + d)) = c;
            } else if (MODE == 1) {
                int b = m >> 10, l = m & 1023;
                float* dstbase;
                int nn;
                if (n < D_MODEL) { dstbase = g_k; nn = n; }
                else             { dstbase = g_v; nn = n - D_MODEL; }
                int h = nn >> 6, d = nn & 63;
                *(float4*)(dstbase + ((((size_t)b * NHEADS + h) * L_ + l) * HDIM + d)) = c;
            } else {
                float4 bg4 = *(const float4*)(bias + n);
                c.x += bg4.x; c.y += bg4.y; c.z += bg4.z; c.w += bg4.w;
                *(float4*)(g_gate + (size_t)m * (2 * D_MODEL) + n) = c;
            }
        }
    }
}

// ---------------------------------------------------------------------------
// Fused attention (flash style). One block = one (b,h) x 64 q-rows.
// 256 threads; thread (ty,tx) owns a 4x4 microtile of the 64x64 S / O tiles.
// SMEM: Qts (d-major, 16KB) + X (K d-major, then reused for P, 16KB)
//       + Y (V row-major, 16KB) = 48KB static exactly.
// Bias added via L1-resident table lookups (no SMEM needed).
// ---------------------------------------------------------------------------
__global__ __launch_bounds__(256)
void attn_kernel()
{
    __shared__ float Qts[64 * 64];   // Qts[d*64 + i], pre-scaled by 1/8
    __shared__ float X  [64 * 64];   // K as Kts[d*64 + j], later P as P[i*64 + j]
    __shared__ float Y  [64 * 64];   // V as Vs[j*64 + d]

    const int bh  = blockIdx.y;      // b*16 + h
    const int h   = bh & (NHEADS - 1);
    const int b   = bh >> 4;
    const int q0  = blockIdx.x * 64;
    const int tid = threadIdx.x;
    const int tx  = tid & 15;
    const int ty  = tid >> 4;

    const float* __restrict__ Qg   = g_q + ((size_t)bh * L_ + q0) * HDIM;
    const float* __restrict__ Kg   = g_k + (size_t)bh * L_ * HDIM;
    const float* __restrict__ Vg   = g_v + (size_t)bh * L_ * HDIM;
    const float* __restrict__ brow = g_biastab + h * BIAS_W;

    // load Q (scaled), transposed to d-major
#pragma unroll
    for (int r = 0; r < 4; r++) {
        int f  = tid + r * 256;          // float4 index, 0..1023
        int i  = f >> 4;
        int d0 = (f & 15) << 2;
        float4 v = *(const float4*)(Qg + (size_t)i * HDIM + d0);
        Qts[(d0 + 0) * 64 + i] = v.x * 0.125f;
        Qts[(d0 + 1) * 64 + i] = v.y * 0.125f;
        Qts[(d0 + 2) * 64 + i] = v.z * 0.125f;
        Qts[(d0 + 3) * 64 + i] = v.w * 0.125f;
    }

    float O[4][4];
    float mi[4], li[4];
#pragma unroll
    for (int ii = 0; ii < 4; ii++) {
        mi[ii] = -1e30f; li[ii] = 0.0f;
#pragma unroll
        for (int jj = 0; jj < 4; jj++) O[ii][jj] = 0.0f;
    }

    for (int t = 0; t < L_ / 64; t++) {
        const int kv0 = t * 64;
        __syncthreads();   // protect X/Y (and Qts on first iter) from prior readers

        // load K transposed into X, V straight into Y
#pragma unroll
        for (int r = 0; r < 4; r++) {
            int f  = tid + r * 256;
            int j  = f >> 4;
            int d0 = (f & 15) << 2;
            float4 kv = *(const float4*)(Kg + (size_t)(kv0 + j) * HDIM + d0);
            X[(d0 + 0) * 64 + j] = kv.x;
            X[(d0 + 1) * 64 + j] = kv.y;
            X[(d0 + 2) * 64 + j] = kv.z;
            X[(d0 + 3) * 64 + j] = kv.w;
            float4 vv = *(const float4*)(Vg + (size_t)(kv0 + j) * HDIM + d0);
            *(float4*)(Y + (size_t)j * 64 + d0) = vv;
        }
        __syncthreads();

        // S = (Q*scale) K^T
        float S[4][4];
#pragma unroll
        for (int ii = 0; ii < 4; ii++)
#pragma unroll
            for (int jj = 0; jj < 4; jj++) S[ii][jj] = 0.0f;

#pragma unroll 8
        for (int d = 0; d < 64; d++) {
            float4 a4 = *(const float4*)(Qts + d * 64 + ty * 4);
            float4 b4 = *(const float4*)(X   + d * 64 + tx * 4);
            float a[4] = {a4.x, a4.y, a4.z, a4.w};
            float bb[4] = {b4.x, b4.y, b4.z, b4.w};
#pragma unroll
            for (int ii = 0; ii < 4; ii++)
#pragma unroll
                for (int jj = 0; jj < 4; jj++)
                    S[ii][jj] = fmaf(a[ii], bb[jj], S[ii][jj]);
        }

        // bias + online softmax (row stats reduced across the 16-lane tx group)
        const int base = kv0 - q0 + (L_ - 1);
#pragma unroll
        for (int ii = 0; ii < 4; ii++) {
            const int i = ty * 4 + ii;
            float mrow = -1e30f;
#pragma unroll
            for (int jj = 0; jj < 4; jj++) {
                const int j = tx * 4 + jj;
                S[ii][jj] += __ldg(brow + base + j - i);
                mrow = fmaxf(mrow, S[ii][jj]);
            }
#pragma unroll
            for (int o = 1; o < 16; o <<= 1)
                mrow = fmaxf(mrow, __shfl_xor_sync(0xffffffffu, mrow, o));
            const float mnew = fmaxf(mi[ii], mrow);
            const float corr = __expf(mi[ii] - mnew);
            mi[ii] = mnew;
            float rs = 0.0f;
#pragma unroll
            for (int jj = 0; jj < 4; jj++) {
                S[ii][jj] = __expf(S[ii][jj] - mnew);
                rs += S[ii][jj];
            }
#pragma unroll
            for (int o = 1; o < 16; o <<= 1)
                rs += __shfl_xor_sync(0xffffffffu, rs, o);
            li[ii] = li[ii] * corr + rs;
#pragma unroll
            for (int jj = 0; jj < 4; jj++) O[ii][jj] *= corr;
        }

        __syncthreads();   // all K reads of X done -> safe to overwrite with P
#pragma unroll
        for (int ii = 0; ii < 4; ii++)
#pragma unroll
            for (int jj = 0; jj < 4; jj++)
                X[(ty * 4 + ii) * 64 + tx * 4 + jj] = S[ii][jj];
        __syncthreads();

        // O += P V
#pragma unroll 8
        for (int j = 0; j < 64; j++) {
            float4 v4 = *(const float4*)(Y + j * 64 + tx * 4);
            float vj[4] = {v4.x, v4.y, v4.z, v4.w};
#pragma unroll
            for (int ii = 0; ii < 4; ii++) {
                float p = X[(ty * 4 + ii) * 64 + j];
#pragma unroll
                for (int jj = 0; jj < 4; jj++)
                    O[ii][jj] = fmaf(p, vj[jj], O[ii][jj]);
            }
        }
    }

    // normalize and store: attn[(b*L + q0+i)][h*64 + d]
#pragma unroll
    for (int ii = 0; ii < 4; ii++) {
        const int i  = ty * 4 + ii;
        const float inv = 1.0f / li[ii];
        float4 o4 = make_float4(O[ii][0] * inv, O[ii][1] * inv,
                                O[ii][2] * inv, O[ii][3] * inv);
        *(float4*)(g_attn + ((size_t)(b * L_ + q0 + i)) * D_MODEL + h * HDIM + tx * 4) = o4;
    }
}

// ---------------------------------------------------------------------------
// Gating: out[m][n] = g[m][n] * sigmoid(g[m][n+1024])
// ---------------------------------------------------------------------------
__global__ __launch_bounds__(256)
void gate_kernel(float* __restrict__ out)
{
    const int idx = blockIdx.x * blockDim.x + threadIdx.x;   // float4 index
    const int m = idx >> 8;
    const int n = (idx & 255) << 2;
    float4 a  = *(const float4*)(g_gate + (size_t)m * (2 * D_MODEL) + n);
    float4 bb = *(const float4*)(g_gate + (size_t)m * (2 * D_MODEL) + D_MODEL + n);
    float4 r;
    r.x = a.x / (1.0f + expf(-bb.x));
    r.y = a.y / (1.0f + expf(-bb.y));
    r.z = a.z / (1.0f + expf(-bb.z));
    r.w = a.w / (1.0f + expf(-bb.w));
    *(float4*)(out + (size_t)m * D_MODEL + n) = r;
}

// ---------------------------------------------------------------------------
// Launch
// ---------------------------------------------------------------------------
extern "C" void kernel_launch(void* const* d_in, const int* in_sizes, int n_in,
                              void* d_out, int out_size)
{
    const float* x_q   = (const float*)d_in[0];
    const float* x_kv  = (const float*)d_in[1];
    const float* Wq    = (const float*)d_in[2];
    const float* Wm    = (const float*)d_in[3];
    const float* Wg    = (const float*)d_in[4];
    const float* bg    = (const float*)d_in[5];
    const float* amp   = (const float*)d_in[6];
    const float* off   = (const float*)d_in[7];
    const float* sharp = (const float*)d_in[8];
    float* out = (float*)d_out;

    // 1) TISA bias table [16][2047]
    tisa_bias_kernel<<<dim3((BIAS_W + 127) / 128, NHEADS), 128>>>(amp, off, sharp);

    // 2) q = x_q @ Wq  -> g_q
    sgemm_kernel<0><<<dim3(D_MODEL / 128, BL / 128), 256>>>(
        x_q, Wq, nullptr, BL, D_MODEL, D_MODEL);

    // 3) mem = x_kv @ Wm -> g_k / g_v
    sgemm_kernel<1><<<dim3(2 * D_MODEL / 128, BL / 128), 256>>>(
        x_kv, Wm, nullptr, BL, 2 * D_MODEL, D_MODEL);

    // 4) fused attention -> g_attn
    attn_kernel<<<dim3(L_ / 64, B_ * NHEADS), 256>>>();

    // 5) g = attn @ Wg + bg -> g_gate
    sgemm_kernel<2><<<dim3(2 * D_MODEL / 128, BL / 128), 256>>>(
        nullptr, Wg, bg, BL, 2 * D_MODEL, D_MODEL);

    // 6) out = a * sigmoid(b)
    gate_kernel<<<(BL * D_MODEL / 4) / 256, 256>>>(out);
}

// round 17
// speedup vs baseline: 1.0001x; 1.0001x over previous
#include <cuda_runtime.h>
#include <math.h>
#include <stdint.h>

// ---------------------------------------------------------------------------
// Problem constants (fixed shapes from the reference)
// ---------------------------------------------------------------------------
#define D_MODEL 1024
#define NHEADS  16
#define HDIM    64
#define NKER    21
#define B_      4
#define L_      1024
#define BL      (B_ * L_)          // 4096 rows
#define BIAS_W  (2 * L_ - 1)       // 2047

// ---------------------------------------------------------------------------
// Scratch (device globals -- no allocation allowed)
// ---------------------------------------------------------------------------
__device__ float g_q   [(size_t)B_ * NHEADS * L_ * HDIM];   // [b][h][l][d]
__device__ float g_k   [(size_t)B_ * NHEADS * L_ * HDIM];
__device__ float g_v   [(size_t)B_ * NHEADS * L_ * HDIM];
__device__ float g_attn[(size_t)BL * D_MODEL];              // [b*l][h*64+d]
__device__ float g_gate[(size_t)BL * 2 * D_MODEL];          // [b*l][2048]
__device__ float g_biastab[NHEADS * BIAS_W];                // [h][rel]

// ---------------------------------------------------------------------------
// TISA bias table: bias[h][r] = sum_j amp*exp(-|sharp|*(d-off)^2), d = r-(L-1)
// ---------------------------------------------------------------------------
__global__ void tisa_bias_kernel(const float* __restrict__ amp,
                                 const float* __restrict__ off,
                                 const float* __restrict__ sharp)
{
    int r = blockIdx.x * blockDim.x + threadIdx.x;
    int h = blockIdx.y;
    if (r >= BIAS_W) return;
    float d = (float)(r - (L_ - 1));
    float s = 0.0f;
#pragma unroll
    for (int j = 0; j < NKER; j++) {
        float a  = amp  [h * NKER + j];
        float o  = off  [h * NKER + j];
        float sh = fabsf(sharp[h * NKER + j]);
        float dd = d - o;
        s += a * expf(-sh * dd * dd);
    }
    g_biastab[h * BIAS_W + r] = s;
}

// ---------------------------------------------------------------------------
// SGEMM: C = A(MxK) * B(KxN) [+bias], 128x128 tile, BK=16, 256 threads,
// 8x8 per-thread microtile, float4 shared paths.
// MODE 0: epilogue scatters into g_q  (head-major [b][h][l][d])
// MODE 1: epilogue scatters into g_k / g_v (cols <1024 -> K, >=1024 -> V)
// MODE 2: A is taken from g_attn, adds bg, writes g_gate row-major
// ---------------------------------------------------------------------------
template <int MODE>
__global__ __launch_bounds__(256)
void sgemm_kernel(const float* __restrict__ Aext,
                  const float* __restrict__ Bmat,
                  const float* __restrict__ bias,
                  int M, int N, int K)
{
    const float* __restrict__ A = (MODE == 2) ? (const float*)g_attn : Aext;

    __shared__ float As[16][128];   // A tile, transposed: As[k][m]
    __shared__ float Bs[16][128];   // B tile: Bs[k][n]

    const int tid  = threadIdx.x;
    const int bm   = blockIdx.y * 128;
    const int bn   = blockIdx.x * 128;
    const int tx   = tid & 15;
    const int ty   = tid >> 4;
    const int row0 = ty * 8;
    const int col0 = tx * 8;

    const int a_row = tid >> 2;          // 0..63
    const int a_col = (tid & 3) << 2;    // 0,4,8,12
    const int b_row = tid >> 5;          // 0..7
    const int b_col = (tid & 31) << 2;   // 0..124

    float acc[8][8];
#pragma unroll
    for (int i = 0; i < 8; i++)
#pragma unroll
        for (int j = 0; j < 8; j++) acc[i][j] = 0.0f;

    for (int k0 = 0; k0 < K; k0 += 16) {
        // load A tile (transpose into shared)
#pragma unroll
        for (int r = 0; r < 2; r++) {
            int row = a_row + r * 64;
            float4 v = *(const float4*)(A + (size_t)(bm + row) * K + (k0 + a_col));
            As[a_col + 0][row] = v.x;
            As[a_col + 1][row] = v.y;
            As[a_col + 2][row] = v.z;
            As[a_col + 3][row] = v.w;
        }
        // load B tile
#pragma unroll
        for (int r = 0; r < 2; r++) {
            int row = b_row + r * 8;
            *(float4*)(&Bs[row][b_col]) =
                *(const float4*)(Bmat + (size_t)(k0 + row) * N + (bn + b_col));
        }
        __syncthreads();

#pragma unroll
        for (int kk = 0; kk < 16; kk++) {
            float4 a0 = *(const float4*)(&As[kk][row0]);
            float4 a1 = *(const float4*)(&As[kk][row0 + 4]);
            float4 b0 = *(const float4*)(&Bs[kk][col0]);
            float4 b1 = *(const float4*)(&Bs[kk][col0 + 4]);
            float a[8] = {a0.x, a0.y, a0.z, a0.w, a1.x, a1.y, a1.z, a1.w};
            float b[8] = {b0.x, b0.y, b0.z, b0.w, b1.x, b1.y, b1.z, b1.w};
#pragma unroll
            for (int i = 0; i < 8; i++)
#pragma unroll
                for (int j = 0; j < 8; j++)
                    acc[i][j] = fmaf(a[i], b[j], acc[i][j]);
        }
        __syncthreads();
    }

    // epilogue: float4 stores; each 4-col group stays inside one head (64-aligned)
#pragma unroll
    for (int i = 0; i < 8; i++) {
        int m = bm + row0 + i;
#pragma unroll
        for (int jh = 0; jh < 2; jh++) {
            int n = bn + col0 + jh * 4;
            float4 c = make_float4(acc[i][jh * 4 + 0], acc[i][jh * 4 + 1],
                                   acc[i][jh * 4 + 2], acc[i][jh * 4 + 3]);
            if (MODE == 0) {
                int b = m >> 10, l = m & 1023;
                int h = n >> 6,  d = n & 63;
                *(float4*)(g_q + ((((size_t)b * NHEADS + h) * L_ + l) * HDIM + d)) = c;
            } else if (MODE == 1) {
                int b = m >> 10, l = m & 1023;
                float* dstbase;
                int nn;
                if (n < D_MODEL) { dstbase = g_k; nn = n; }
                else             { dstbase = g_v; nn = n - D_MODEL; }
                int h = nn >> 6, d = nn & 63;
                *(float4*)(dstbase + ((((size_t)b * NHEADS + h) * L_ + l) * HDIM + d)) = c;
            } else {
                float4 bg4 = *(const float4*)(bias + n);
                c.x += bg4.x; c.y += bg4.y; c.z += bg4.z; c.w += bg4.w;
                *(float4*)(g_gate + (size_t)m * (2 * D_MODEL) + n) = c;
            }
        }
    }
}

// ---------------------------------------------------------------------------
// Fused attention (flash style). One block = one (b,h) x 64 q-rows.
// 256 threads; thread (ty,tx) owns a 4x4 microtile of the 64x64 S / O tiles.
// SMEM: Qts (d-major, 16KB) + X (K d-major, then reused for P, 16KB)
//       + Y (V row-major, 16KB) = 48KB static exactly.
// Bias added via L1-resident table lookups (no SMEM needed).
// ---------------------------------------------------------------------------
__global__ __launch_bounds__(256)
void attn_kernel()
{
    __shared__ float Qts[64 * 64];   // Qts[d*64 + i], pre-scaled by 1/8
    __shared__ float X  [64 * 64];   // K as Kts[d*64 + j], later P as P[i*64 + j]
    __shared__ float Y  [64 * 64];   // V as Vs[j*64 + d]

    const int bh  = blockIdx.y;      // b*16 + h
    const int h   = bh & (NHEADS - 1);
    const int b   = bh >> 4;
    const int q0  = blockIdx.x * 64;
    const int tid = threadIdx.x;
    const int tx  = tid & 15;
    const int ty  = tid >> 4;

    const float* __restrict__ Qg   = g_q + ((size_t)bh * L_ + q0) * HDIM;
    const float* __restrict__ Kg   = g_k + (size_t)bh * L_ * HDIM;
    const float* __restrict__ Vg   = g_v + (size_t)bh * L_ * HDIM;
    const float* __restrict__ brow = g_biastab + h * BIAS_W;

    // load Q (scaled), transposed to d-major
#pragma unroll
    for (int r = 0; r < 4; r++) {
        int f  = tid + r * 256;          // float4 index, 0..1023
        int i  = f >> 4;
        int d0 = (f & 15) << 2;
        float4 v = *(const float4*)(Qg + (size_t)i * HDIM + d0);
        Qts[(d0 + 0) * 64 + i] = v.x * 0.125f;
        Qts[(d0 + 1) * 64 + i] = v.y * 0.125f;
        Qts[(d0 + 2) * 64 + i] = v.z * 0.125f;
        Qts[(d0 + 3) * 64 + i] = v.w * 0.125f;
    }

    float O[4][4];
    float mi[4], li[4];
#pragma unroll
    for (int ii = 0; ii < 4; ii++) {
        mi[ii] = -1e30f; li[ii] = 0.0f;
#pragma unroll
        for (int jj = 0; jj < 4; jj++) O[ii][jj] = 0.0f;
    }

    for (int t = 0; t < L_ / 64; t++) {
        const int kv0 = t * 64;
        __syncthreads();   // protect X/Y (and Qts on first iter) from prior readers

        // load K transposed into X, V straight into Y
#pragma unroll
        for (int r = 0; r < 4; r++) {
            int f  = tid + r * 256;
            int j  = f >> 4;
            int d0 = (f & 15) << 2;
            float4 kv = *(const float4*)(Kg + (size_t)(kv0 + j) * HDIM + d0);
            X[(d0 + 0) * 64 + j] = kv.x;
            X[(d0 + 1) * 64 + j] = kv.y;
            X[(d0 + 2) * 64 + j] = kv.z;
            X[(d0 + 3) * 64 + j] = kv.w;
            float4 vv = *(const float4*)(Vg + (size_t)(kv0 + j) * HDIM + d0);
            *(float4*)(Y + (size_t)j * 64 + d0) = vv;
        }
        __syncthreads();

        // S = (Q*scale) K^T
        float S[4][4];
#pragma unroll
        for (int ii = 0; ii < 4; ii++)
#pragma unroll
            for (int jj = 0; jj < 4; jj++) S[ii][jj] = 0.0f;

#pragma unroll 8
        for (int d = 0; d < 64; d++) {
            float4 a4 = *(const float4*)(Qts + d * 64 + ty * 4);
            float4 b4 = *(const float4*)(X   + d * 64 + tx * 4);
            float a[4] = {a4.x, a4.y, a4.z, a4.w};
            float bb[4] = {b4.x, b4.y, b4.z, b4.w};
#pragma unroll
            for (int ii = 0; ii < 4; ii++)
#pragma unroll
                for (int jj = 0; jj < 4; jj++)
                    S[ii][jj] = fmaf(a[ii], bb[jj], S[ii][jj]);
        }

        // bias + online softmax (row stats reduced across the 16-lane tx group)
        const int base = kv0 - q0 + (L_ - 1);
#pragma unroll
        for (int ii = 0; ii < 4; ii++) {
            const int i = ty * 4 + ii;
            float mrow = -1e30f;
#pragma unroll
            for (int jj = 0; jj < 4; jj++) {
                const int j = tx * 4 + jj;
                S[ii][jj] += __ldg(brow + base + j - i);
                mrow = fmaxf(mrow, S[ii][jj]);
            }
#pragma unroll
            for (int o = 1; o < 16; o <<= 1)
                mrow = fmaxf(mrow, __shfl_xor_sync(0xffffffffu, mrow, o));
            const float mnew = fmaxf(mi[ii], mrow);
            const float corr = __expf(mi[ii] - mnew);
            mi[ii] = mnew;
            float rs = 0.0f;
#pragma unroll
            for (int jj = 0; jj < 4; jj++) {
                S[ii][jj] = __expf(S[ii][jj] - mnew);
                rs += S[ii][jj];
            }
#pragma unroll
            for (int o = 1; o < 16; o <<= 1)
                rs += __shfl_xor_sync(0xffffffffu, rs, o);
            li[ii] = li[ii] * corr + rs;
#pragma unroll
            for (int jj = 0; jj < 4; jj++) O[ii][jj] *= corr;
        }

        __syncthreads();   // all K reads of X done -> safe to overwrite with P
#pragma unroll
        for (int ii = 0; ii < 4; ii++)
#pragma unroll
            for (int jj = 0; jj < 4; jj++)
                X[(ty * 4 + ii) * 64 + tx * 4 + jj] = S[ii][jj];
        __syncthreads();

        // O += P V
#pragma unroll 8
        for (int j = 0; j < 64; j++) {
            float4 v4 = *(const float4*)(Y + j * 64 + tx * 4);
            float vj[4] = {v4.x, v4.y, v4.z, v4.w};
#pragma unroll
            for (int ii = 0; ii < 4; ii++) {
                float p = X[(ty * 4 + ii) * 64 + j];
#pragma unroll
                for (int jj = 0; jj < 4; jj++)
                    O[ii][jj] = fmaf(p, vj[jj], O[ii][jj]);
            }
        }
    }

    // normalize and store: attn[(b*L + q0+i)][h*64 + d]
#pragma unroll
    for (int ii = 0; ii < 4; ii++) {
        const int i  = ty * 4 + ii;
        const float inv = 1.0f / li[ii];
        float4 o4 = make_float4(O[ii][0] * inv, O[ii][1] * inv,
                                O[ii][2] * inv, O[ii][3] * inv);
        *(float4*)(g_attn + ((size_t)(b * L_ + q0 + i)) * D_MODEL + h * HDIM + tx * 4) = o4;
    }
}

// ---------------------------------------------------------------------------
// Gating: out[m][n] = g[m][n] * sigmoid(g[m][n+1024])
// ---------------------------------------------------------------------------
__global__ __launch_bounds__(256)
void gate_kernel(float* __restrict__ out)
{
    const int idx = blockIdx.x * blockDim.x + threadIdx.x;   // float4 index
    const int m = idx >> 8;
    const int n = (idx & 255) << 2;
    float4 a  = *(const float4*)(g_gate + (size_t)m * (2 * D_MODEL) + n);
    float4 bb = *(const float4*)(g_gate + (size_t)m * (2 * D_MODEL) + D_MODEL + n);
    float4 r;
    r.x = a.x / (1.0f + expf(-bb.x));
    r.y = a.y / (1.0f + expf(-bb.y));
    r.z = a.z / (1.0f + expf(-bb.z));
    r.w = a.w / (1.0f + expf(-bb.w));
    *(float4*)(out + (size_t)m * D_MODEL + n) = r;
}

// ---------------------------------------------------------------------------
// Launch
// ---------------------------------------------------------------------------
extern "C" void kernel_launch(void* const* d_in, const int* in_sizes, int n_in,
                              void* d_out, int out_size)
{
    const float* x_q   = (const float*)d_in[0];
    const float* x_kv  = (const float*)d_in[1];
    const float* Wq    = (const float*)d_in[2];
    const float* Wm    = (const float*)d_in[3];
    const float* Wg    = (const float*)d_in[4];
    const float* bg    = (const float*)d_in[5];
    const float* amp   = (const float*)d_in[6];
    const float* off   = (const float*)d_in[7];
    const float* sharp = (const float*)d_in[8];
    float* out = (float*)d_out;

    // 1) TISA bias table [16][2047]
    tisa_bias_kernel<<<dim3((BIAS_W + 127) / 128, NHEADS), 128>>>(amp, off, sharp);

    // 2) q = x_q @ Wq  -> g_q
    sgemm_kernel<0><<<dim3(D_MODEL / 128, BL / 128), 256>>>(
        x_q, Wq, nullptr, BL, D_MODEL, D_MODEL);

    // 3) mem = x_kv @ Wm -> g_k / g_v
    sgemm_kernel<1><<<dim3(2 * D_MODEL / 128, BL / 128), 256>>>(
        x_kv, Wm, nullptr, BL, 2 * D_MODEL, D_MODEL);

    // 4) fused attention -> g_attn
    attn_kernel<<<dim3(L_ / 64, B_ * NHEADS), 256>>>();

    // 5) g = attn @ Wg + bg -> g_gate
    sgemm_kernel<2><<<dim3(2 * D_MODEL / 128, BL / 128), 256>>>(
        nullptr, Wg, bg, BL, 2 * D_MODEL, D_MODEL);

    // 6) out = a * sigmoid(b)
    gate_kernel<<<(BL * D_MODEL / 4) / 256, 256>>>(out);
}